// round 4
// baseline (speedup 1.0000x reference)
#include <cuda_runtime.h>
#include <math.h>

#define NB 4
#define NBLOG 2
#define KB 2
#define DB 2
#define KI 6
#define DI 5
#define ACCB (KB*(DB+1))   /* 6  */
#define ACCI (KI*(DI+1))   /* 36 */
#define TWO_DELTA_D 6.0f
#define DELTA_V 0.5f
#define PARAM_REG 0.001f
#define MAXLAB (4*512*1024)

// ---------------- device scratch (no allocation allowed) --------------------
__device__ float g_bin_acc [NB][ACCB];
__device__ float g_inst_acc[NB][ACCI];
__device__ float g_bin_var [NB][KB];
__device__ float g_inst_var[NB][KI];
__device__ float g_bin_mean [NB][KB*DB];
__device__ float g_inst_mean[NB][KI*DI];
__device__ float g_bin_rest [NB];
__device__ float g_inst_rest[NB];
__device__ int   g_is64[2];
__device__ unsigned g_cnt0, g_cnt1;
__device__ volatile unsigned g_rel0;
__device__ unsigned char g_plab_bin [MAXLAB];
__device__ unsigned char g_plab_inst[MAXLAB];

__device__ __forceinline__ float f4c(const float4& v, int p) {
    return p == 0 ? v.x : (p == 1 ? v.y : (p == 2 ? v.z : v.w));
}

// ---------------- kernel 0: zero scratch + detect label dtype ---------------
__global__ void init_kernel(const int* __restrict__ binlab,
                            const int* __restrict__ instlab) {
    int t = threadIdx.x;
    float* pb = &g_bin_acc[0][0];
    for (int j = t; j < NB*ACCB; j += blockDim.x) pb[j] = 0.f;
    float* pi = &g_inst_acc[0][0];
    for (int j = t; j < NB*ACCI; j += blockDim.x) pi[j] = 0.f;
    float* vb = &g_bin_var[0][0];
    for (int j = t; j < NB*KB; j += blockDim.x) vb[j] = 0.f;
    float* vi = &g_inst_var[0][0];
    for (int j = t; j < NB*KI; j += blockDim.x) vi[j] = 0.f;
    if (t == 0) {
        g_cnt0 = 0u; g_cnt1 = 0u; g_rel0 = 0u;
        // int64 little-endian => odd 32-bit words of first 64 elems all zero.
        // int32 random labels => P(all zero) <= 2^-64.
        int b64 = 1, i64 = 1;
        for (int j = 0; j < 64; j++) {
            if (binlab [2*j + 1] != 0) b64 = 0;
            if (instlab[2*j + 1] != 0) i64 = 0;
        }
        g_is64[0] = b64;
        g_is64[1] = i64;
    }
}

// ---------------- phase A: sums + counts + label packing --------------------
template<int K, int D>
__device__ __forceinline__ void phaseA(const float* __restrict__ base,
                                       const void*  __restrict__ labels,
                                       size_t labvec,
                                       unsigned char* __restrict__ plab,
                                       float* __restrict__ gacc,
                                       int is64, int nvec, int MN,
                                       int t0, int stride, float* red) {
    constexpr int ACC = K*(D+1);
    float acc[ACC];
#pragma unroll
    for (int j = 0; j < ACC; j++) acc[j] = 0.f;

    for (int i = t0; i < nvec; i += stride) {
        float4 x[D];
#pragma unroll
        for (int d = 0; d < D; d++)
            x[d] = ((const float4*)(base + (size_t)d*MN))[i];
        int lab[4];
        if (is64) {
            const longlong4 v = ((const longlong4*)labels)[labvec + i];
            lab[0]=(int)v.x; lab[1]=(int)v.y; lab[2]=(int)v.z; lab[3]=(int)v.w;
        } else {
            const int4 v = ((const int4*)labels)[labvec + i];
            lab[0]=v.x; lab[1]=v.y; lab[2]=v.z; lab[3]=v.w;
        }
        uchar4 pc;
        pc.x = (unsigned char)lab[0]; pc.y = (unsigned char)lab[1];
        pc.z = (unsigned char)lab[2]; pc.w = (unsigned char)lab[3];
        ((uchar4*)plab)[labvec + i] = pc;
#pragma unroll
        for (int p = 0; p < 4; p++) {
#pragma unroll
            for (int k = 0; k < K; k++) {
                float m = (lab[p] == k) ? 1.0f : 0.0f;
#pragma unroll
                for (int d = 0; d < D; d++)
                    acc[k*(D+1)+d] = fmaf(m, f4c(x[d], p), acc[k*(D+1)+d]);
                acc[k*(D+1)+D] += m;
            }
        }
    }
    // block reduce -> one global atomic per accumulator
#pragma unroll
    for (int j = 0; j < ACC; j++) {
        float v = acc[j];
#pragma unroll
        for (int o = 16; o; o >>= 1) v += __shfl_xor_sync(0xffffffffu, v, o);
        acc[j] = v;
    }
    __syncthreads();
    if (threadIdx.x < ACC) red[threadIdx.x] = 0.f;
    __syncthreads();
    if ((threadIdx.x & 31) == 0) {
#pragma unroll
        for (int j = 0; j < ACC; j++) atomicAdd(&red[j], acc[j]);
    }
    __syncthreads();
    if (threadIdx.x < ACC) atomicAdd(&gacc[threadIdx.x], red[threadIdx.x]);
    __syncthreads();
}

// ---------------- phase B: hinge variance (means in smem) -------------------
template<int K, int D>
__device__ __forceinline__ void phaseB(const float* __restrict__ base,
                                       const unsigned char* __restrict__ plab,
                                       size_t labvec,
                                       const float* __restrict__ smean,
                                       float* __restrict__ gvar,
                                       int nvec, int MN,
                                       int t0, int stride, float* red) {
    float accv[K];
#pragma unroll
    for (int k = 0; k < K; k++) accv[k] = 0.f;

    for (int i = t0; i < nvec; i += stride) {
        float4 x[D];
#pragma unroll
        for (int d = 0; d < D; d++)
            x[d] = ((const float4*)(base + (size_t)d*MN))[i];
        const uchar4 pc = ((const uchar4*)plab)[labvec + i];
        int lab[4] = {pc.x, pc.y, pc.z, pc.w};
#pragma unroll
        for (int p = 0; p < 4; p++) {
            const float* mu = smean + lab[p]*D;   // dynamic smem lookup (LSU pipe)
            float dist2 = 0.f;
#pragma unroll
            for (int d = 0; d < D; d++) {
                float df = f4c(x[d], p) - mu[d];
                dist2 = fmaf(df, df, dist2);
            }
            float h  = fmaxf(sqrtf(dist2) - DELTA_V, 0.f);
            float h2 = h*h;
#pragma unroll
            for (int k = 0; k < K; k++)
                accv[k] += (lab[p] == k) ? h2 : 0.f;
        }
    }
#pragma unroll
    for (int k = 0; k < K; k++) {
        float v = accv[k];
#pragma unroll
        for (int o = 16; o; o >>= 1) v += __shfl_xor_sync(0xffffffffu, v, o);
        accv[k] = v;
    }
    __syncthreads();
    if (threadIdx.x < K) red[threadIdx.x] = 0.f;
    __syncthreads();
    if ((threadIdx.x & 31) == 0) {
#pragma unroll
        for (int k = 0; k < K; k++) atomicAdd(&red[k], accv[k]);
    }
    __syncthreads();
    if (threadIdx.x < K) atomicAdd(&gvar[threadIdx.x], red[threadIdx.x]);
    __syncthreads();
}

// push + reg terms from a [K*D] mean array
template<int K, int D>
__device__ __forceinline__ float rest_terms(const float* mean) {
    float ld = 0.f;
    for (int i = 0; i < K; i++)
        for (int j = 0; j < K; j++) if (i != j) {
            float s = 0.f;
            for (int d = 0; d < D; d++) {
                float df = mean[i*D+d] - mean[j*D+d];
                s += df*df;
            }
            float dn = fmaxf(TWO_DELTA_D - sqrtf(s), 0.f);
            ld += dn*dn;
        }
    ld /= (float)(K*(K-1));
    float lr = 0.f;
    for (int k = 0; k < K; k++) {
        float s = 0.f;
        for (int d = 0; d < D; d++) s += mean[k*D+d]*mean[k*D+d];
        lr += sqrtf(s);
    }
    lr /= (float)K;
    return ld + PARAM_REG * lr;
}

// ---------------- the single fused persistent kernel ------------------------
__global__ __launch_bounds__(256)
void fused_kernel(const float* __restrict__ binL,  const void* __restrict__ binlab,
                  const float* __restrict__ instL, const void* __restrict__ instlab,
                  float* __restrict__ out, int MN) {
    __shared__ float red[ACCI];
    __shared__ float smb[KB*DB];
    __shared__ float smi[KI*DI];
    __shared__ unsigned lastsh;

    const int nvec   = MN >> 2;
    const int b      = blockIdx.x & (NB-1);
    const int rb     = blockIdx.x >> NBLOG;
    const int bpb    = gridDim.x >> NBLOG;
    const int stride = bpb * blockDim.x;
    const int t0     = rb * blockDim.x + threadIdx.x;
    const size_t lv  = (size_t)b * nvec;

    const float* binb  = binL  + (size_t)b * DB * MN;
    const float* instb = instL + (size_t)b * DI * MN;

    // ===== phase A: sums/counts + label packing =====
    phaseA<KB,DB>(binb,  binlab,  lv, g_plab_bin,  &g_bin_acc [b][0], g_is64[0], nvec, MN, t0, stride, red);
    phaseA<KI,DI>(instb, instlab, lv, g_plab_inst, &g_inst_acc[b][0], g_is64[1], nvec, MN, t0, stride, red);

    // ===== grid barrier 1; last block computes means + rest =====
    if (threadIdx.x == 0) {
        __threadfence();
        unsigned p = atomicAdd(&g_cnt0, 1u);
        lastsh = (p == gridDim.x - 1u) ? 1u : 0u;
        if (!lastsh) {
            while (g_rel0 == 0u) __nanosleep(64);
        }
    }
    __syncthreads();
    if (lastsh) {
        if (threadIdx.x == 0) {
            for (int bb = 0; bb < NB; bb++) {
                for (int k = 0; k < KB; k++) {
                    float c = __ldcg(&g_bin_acc[bb][k*(DB+1)+DB]);
                    for (int d = 0; d < DB; d++)
                        g_bin_mean[bb][k*DB+d] = __ldcg(&g_bin_acc[bb][k*(DB+1)+d]) / c;
                }
                for (int k = 0; k < KI; k++) {
                    float c = __ldcg(&g_inst_acc[bb][k*(DI+1)+DI]);
                    for (int d = 0; d < DI; d++)
                        g_inst_mean[bb][k*DI+d] = __ldcg(&g_inst_acc[bb][k*(DI+1)+d]) / c;
                }
                g_bin_rest [bb] = rest_terms<KB,DB>(&g_bin_mean [bb][0]);
                g_inst_rest[bb] = rest_terms<KI,DI>(&g_inst_mean[bb][0]);
            }
            __threadfence();
            g_rel0 = 1u;
        }
        __syncthreads();
    }

    // load this batch's means into smem
    if (threadIdx.x < KB*DB) smb[threadIdx.x] = __ldcg(&g_bin_mean [b][threadIdx.x]);
    if (threadIdx.x < KI*DI) smi[threadIdx.x] = __ldcg(&g_inst_mean[b][threadIdx.x]);
    __syncthreads();

    // ===== phase B: hinge variance sums =====
    phaseB<KB,DB>(binb,  g_plab_bin,  lv, smb, &g_bin_var [b][0], nvec, MN, t0, stride, red);
    phaseB<KI,DI>(instb, g_plab_inst, lv, smi, &g_inst_var[b][0], nvec, MN, t0, stride, red);

    // ===== barrier 2 (arrive only); last block writes output =====
    if (threadIdx.x == 0) {
        __threadfence();
        unsigned p = atomicAdd(&g_cnt1, 1u);
        if (p == gridDim.x - 1u) {
            float bl = 0.f;
            for (int bb = 0; bb < NB; bb++) {
                float lvv = 0.f;
                for (int k = 0; k < KB; k++)
                    lvv += __ldcg(&g_bin_var[bb][k]) / __ldcg(&g_bin_acc[bb][k*(DB+1)+DB]);
                bl += lvv / (float)KB + g_bin_rest[bb];
            }
            out[0] = bl / (float)NB;
            float il = 0.f;
            for (int bb = 0; bb < NB; bb++) {
                float lvv = 0.f;
                for (int k = 0; k < KI; k++)
                    lvv += __ldcg(&g_inst_var[bb][k]) / __ldcg(&g_inst_acc[bb][k*(DI+1)+DI]);
                il += lvv / (float)KI + g_inst_rest[bb];
            }
            out[1] = il / (float)NB;
        }
    }
}

// ---------------- launch -----------------------------------------------------
extern "C" void kernel_launch(void* const* d_in, const int* in_sizes, int n_in,
                              void* d_out, int out_size) {
    const float* bin_logits  = (const float*)d_in[0];
    const void*  bin_labels  = d_in[1];
    const float* inst_logits = (const float*)d_in[2];
    const void*  inst_labels = d_in[3];
    float* out = (float*)d_out;

    const int MN = in_sizes[1] / NB;

    // size the persistent grid so every CTA is co-resident (barrier safety)
    int dev = 0;
    cudaGetDevice(&dev);
    int sms = 0;
    cudaDeviceGetAttribute(&sms, cudaDevAttrMultiProcessorCount, dev);
    int perSM = 0;
    cudaOccupancyMaxActiveBlocksPerMultiprocessor(&perSM, fused_kernel, 256, 0);
    if (perSM < 1) perSM = 1;
    int blocks = sms * perSM;
    blocks -= blocks % NB;
    if (blocks < NB) blocks = NB;

    init_kernel<<<1, 256>>>((const int*)bin_labels, (const int*)inst_labels);
    fused_kernel<<<blocks, 256>>>(bin_logits, bin_labels, inst_logits, inst_labels, out, MN);
}